// round 13
// baseline (speedup 1.0000x reference)
#include <cuda_runtime.h>
#include <cuda_bf16.h>
#include <cstdint>

// TELIF: temporal-encoded LIF neuron scan.
//   tx : [T, B, N] float32   (T=512, B=64, N=1024)
//   TE : [N, T]    float32
//   out: [T, B, N] float32 spikes
//
// Kernel 1: transpose TE -> g_TEt (coalesced, L2-resident in the scan).
// Kernel 2: scan. tx is pipelined gmem->smem with cp.async in a depth-8
// per-chunk ring. Copies are WARP-LOCAL (each warp copies exactly what it
// consumes), so completion needs only cp.async.wait_group + __syncwarp —
// no block barriers, and the wait is precise on the OLDEST chunk only
// (register LDG pipelines can't express this: 6 scoreboard slots force
// shared wait-masks). TE uses a distance-4 register pipeline (L2 hits).

#define T_STEPS 512
#define B_DIM   64
#define N_DIM   1024
#define BN      (B_DIM * N_DIM)      // 65536
#define U       4                    // timesteps per chunk
#define NCHUNK  (T_STEPS / U)        // 128
#define BLK     128
#define DEPTH   8                    // tx smem ring depth (chunks)

#define REST      0.0f
#define DECAY     0.2f
#define THRESHOLD 0.3f
#define BETA      0.02f

// Transposed temporal encoding: TEt[t][n]  (2 MB static device scratch)
__device__ float g_TEt[T_STEPS * N_DIM];

// ---------------------------------------------------------------------------
// Pre-pass: transpose TE [N, T] -> g_TEt [T, N].
// ---------------------------------------------------------------------------
__global__ void transpose_te_kernel(const float* __restrict__ TE) {
    __shared__ float tile[32][33];
    const int tbase = blockIdx.x * 32;
    const int nbase = blockIdx.y * 32;

    #pragma unroll
    for (int r = threadIdx.y; r < 32; r += 8)
        tile[r][threadIdx.x] = TE[(nbase + r) * T_STEPS + tbase + threadIdx.x];
    __syncthreads();
    #pragma unroll
    for (int r = threadIdx.y; r < 32; r += 8)
        __stcs(&g_TEt[(tbase + r) * N_DIM + nbase + threadIdx.x],
               tile[threadIdx.x][r]);
}

// ---------------------------------------------------------------------------
// cp.async helpers
// ---------------------------------------------------------------------------
__device__ __forceinline__ void cp_async16(uint32_t dst, const void* src) {
    asm volatile("cp.async.cg.shared.global [%0], [%1], 16;"
                 :: "r"(dst), "l"(src));
}
#define CP_COMMIT()  asm volatile("cp.async.commit_group;" ::: "memory")
#define CP_WAIT(nn)  asm volatile("cp.async.wait_group " #nn ";" ::: "memory")

// ---- issue tx chunk c into ring slot c%DEPTH (one cp.async16 per thread) --
// lane l of warp w copies row (l>>3), 16B segment (l&7) of the warp's own
// 32-column slice -> 4 coalesced 128B lines per warp-op, consumed warp-local.
#define TX_ASYNC(c)                                                           \
    {                                                                         \
        const int slot = (c) & (DEPTH - 1);                                   \
        cp_async16(smem_base +                                                \
                       (uint32_t)(((slot * U + row_) * BLK + seg_) * 4u),     \
                   tx + (size_t)((c) * U + row_) * BN + gseg_);               \
        CP_COMMIT();                                                          \
    }

// ---- TE chunk load (register pipeline, L2-resident) -----------------------
#define LOAD_TE(tq, c)                                                        \
    {                                                                         \
        _Pragma("unroll")                                                     \
        for (int u = 0; u < U; u++)                                           \
            tq[u] = g_TEt[((c) * U + u) * N_DIM + n];                         \
    }

// ---- one chunk of the recurrence (math form measured rel_err == 0.0) ------
#define COMPUTE_CHUNK(tq, c)                                                  \
    {                                                                         \
        const int slot = (c) & (DEPTH - 1);                                   \
        _Pragma("unroll")                                                     \
        for (int u = 0; u < U; u++) {                                         \
            const float x  = s_tx[slot][u][threadIdx.x];                      \
            const float te = tq[u];                                           \
            th = th + v * te - (th - THRESHOLD) * BETA;                       \
            const float vd = v * DECAY + x;                                   \
            v  = (y != 0.0f) ? x : vd;                                        \
            y  = (v > th) ? 1.0f : 0.0f;                                      \
            __stcs(&ty[((c) * U + u) * BN + g], y);                           \
        }                                                                     \
    }

// wait for oldest pending chunk, make the warp's copies visible
#define ARRIVE(nn)  { CP_WAIT(nn); __syncwarp(); }

__global__ void __launch_bounds__(BLK) telif_kernel(
    const float* __restrict__ tx,
    float* __restrict__ ty)
{
    __shared__ float s_tx[DEPTH][U][BLK];   // 16 KB ring

    const int g    = blockIdx.x * BLK + threadIdx.x;   // g = b*N + n
    const int n    = g & (N_DIM - 1);
    const int lane = threadIdx.x & 31;
    const int w    = threadIdx.x >> 5;

    // copy mapping (constant per thread)
    const int row_  = lane >> 3;                 // 0..3  (timestep within chunk)
    const int seg_  = w * 32 + (lane & 7) * 4;   // float index within 128-col row
    const int gseg_ = blockIdx.x * BLK + seg_;   // global float index of segment
    const uint32_t smem_base = (uint32_t)__cvta_generic_to_shared(s_tx);

    float v  = REST;
    float y  = 0.0f;
    float th = THRESHOLD;

    float teA[U], teB[U], teC[U], teD[U];

    // prologue: 7 tx chunks in flight, 4 TE chunks in registers
    TX_ASYNC(0) TX_ASYNC(1) TX_ASYNC(2) TX_ASYNC(3)
    TX_ASYNC(4) TX_ASYNC(5) TX_ASYNC(6)
    LOAD_TE(teA, 0) LOAD_TE(teB, 1) LOAD_TE(teC, 2) LOAD_TE(teD, 3)

    // steady state: guard-free (c <= 116 -> issues chunks <= 126, TE <= 123)
    #pragma unroll 1
    for (int c = 0; c < NCHUNK - 8; c += 4) {
        TX_ASYNC(c + 7)  ARRIVE(7) COMPUTE_CHUNK(teA, c)     LOAD_TE(teA, c + 4)
        TX_ASYNC(c + 8)  ARRIVE(7) COMPUTE_CHUNK(teB, c + 1) LOAD_TE(teB, c + 5)
        TX_ASYNC(c + 9)  ARRIVE(7) COMPUTE_CHUNK(teC, c + 2) LOAD_TE(teC, c + 6)
        TX_ASYNC(c + 10) ARRIVE(7) COMPUTE_CHUNK(teD, c + 3) LOAD_TE(teD, c + 7)
    }

    // drain: chunks 120..127 (last tx issue is 127; wait counts shrink)
    TX_ASYNC(127) ARRIVE(7) COMPUTE_CHUNK(teA, 120) LOAD_TE(teA, 124)
    ARRIVE(6) COMPUTE_CHUNK(teB, 121) LOAD_TE(teB, 125)
    ARRIVE(5) COMPUTE_CHUNK(teC, 122) LOAD_TE(teC, 126)
    ARRIVE(4) COMPUTE_CHUNK(teD, 123) LOAD_TE(teD, 127)
    ARRIVE(3) COMPUTE_CHUNK(teA, 124)
    ARRIVE(2) COMPUTE_CHUNK(teB, 125)
    ARRIVE(1) COMPUTE_CHUNK(teC, 126)
    ARRIVE(0) COMPUTE_CHUNK(teD, 127)
}

// ---------------------------------------------------------------------------
extern "C" void kernel_launch(void* const* d_in, const int* in_sizes, int n_in,
                              void* d_out, int out_size) {
    const float* tx = (const float*)d_in[0];   // [T, B, N]
    const float* TE = (const float*)d_in[1];   // [N, T]
    float* ty = (float*)d_out;                 // [T, B, N]
    (void)in_sizes; (void)n_in; (void)out_size;

    dim3 tgrid(T_STEPS / 32, N_DIM / 32);
    dim3 tblock(32, 8);
    transpose_te_kernel<<<tgrid, tblock>>>(TE);

    telif_kernel<<<BN / BLK, BLK>>>(tx, ty);
}

// round 14
// speedup vs baseline: 1.1189x; 1.1189x over previous
#include <cuda_runtime.h>
#include <cuda_bf16.h>
#include <cstdint>

// TELIF: temporal-encoded LIF neuron scan — single kernel, no block barriers.
//   tx : [T, B, N] float32   (T=512, B=64, N=1024)
//   TE : [N, T]    float32
//   out: [T, B, N] float32 spikes
//
// Per (b, n), sequential in t:
//   th = th + v*TE[n,t] - (th - THRESHOLD)*BETA
//   v  = v*DECAY*(1 - y) + x
//   y  = (v > th) ? 1 : 0
//
// Both input streams are pipelined gmem->smem with cp.async, and BOTH are
// warp-local (each warp copies exactly the rows its own lanes consume), so
// completion needs only cp.async.wait_group + __syncwarp — no __syncthreads
// anywhere, and waits are precise on the oldest commit group only.
//  - tx: depth-8 ring of 4-timestep chunks (one 16B op/thread/chunk).
//  - TE: double-buffered 32-timestep x 128-row tiles read directly from the
//    native [N,T] layout (128B per row -> 4 full lines per warp-op; L2 hits,
//    64 blocks share each slice). Tile T+1 rides in the SAME commit group as
//    tx chunk 8T+7 (7-chunk lead), so group accounting is unchanged.

#define T_STEPS 512
#define B_DIM   64
#define N_DIM   1024
#define BN      (B_DIM * N_DIM)      // 65536
#define U       4                    // timesteps per chunk
#define NCHUNK  (T_STEPS / U)        // 128
#define BLK     128
#define DEPTH   8                    // tx ring depth (chunks)
#define TS_TILE 32                   // timesteps per TE tile (= 8 chunks)
#define TEPAD   36                   // floats per TE smem row (conflict-free)

#define REST      0.0f
#define DECAY     0.2f
#define THRESHOLD 0.3f
#define BETA      0.02f

// ---------------------------------------------------------------------------
__device__ __forceinline__ void cp_async16(uint32_t dst, const void* src) {
    asm volatile("cp.async.cg.shared.global [%0], [%1], 16;"
                 :: "r"(dst), "l"(src));
}
#define CP_COMMIT()  asm volatile("cp.async.commit_group;" ::: "memory")
#define CP_WAIT(nn)  asm volatile("cp.async.wait_group " #nn ";" ::: "memory")
#define ARRIVE(nn)   { CP_WAIT(nn); __syncwarp(); }

// ---- TE tile T -> smem buffer T&1 (8 warp-local ops; NO commit: rides in
//      the next TX_ASYNC's group) --------------------------------------------
#define TE_ASYNC(T)                                                          \
    {                                                                        \
        const int bb = (T) & 1;                                              \
        _Pragma("unroll")                                                    \
        for (int j = 0; j < 8; j++) {                                        \
            const int rt = w * 32 + j * 4 + (lane >> 3);                     \
            cp_async16(smem_te +                                             \
                           (uint32_t)(((bb * BLK + rt) * TEPAD               \
                                       + (lane & 7) * 4) * 4u),              \
                       TE + (size_t)(n0 + rt) * T_STEPS + (T) * TS_TILE      \
                          + (lane & 7) * 4);                                 \
        }                                                                    \
    }

// ---- tx chunk c -> ring slot c%DEPTH (one 16B op/thread) + commit ---------
#define TX_ASYNC(c)                                                          \
    {                                                                        \
        const int slot = (c) & (DEPTH - 1);                                  \
        cp_async16(smem_tx +                                                 \
                       (uint32_t)(((slot * U + row_) * BLK + seg_) * 4u),    \
                   tx + (size_t)((c) * U + row_) * BN + gseg_);              \
        CP_COMMIT();                                                         \
    }

// ---- one chunk of the recurrence (math form measured rel_err == 0.0) ------
#define COMPUTE_CHUNK(c)                                                     \
    {                                                                        \
        const int slot = (c) & (DEPTH - 1);                                  \
        const float4 t4 = *reinterpret_cast<const float4*>(                  \
            &s_te[((c) >> 3) & 1][threadIdx.x][((c) & 7) * 4]);              \
        _Pragma("unroll")                                                    \
        for (int u = 0; u < U; u++) {                                        \
            const float x  = s_tx[slot][u][threadIdx.x];                     \
            const float te = (u == 0) ? t4.x : (u == 1) ? t4.y               \
                           : (u == 2) ? t4.z : t4.w;                         \
            th = th + v * te - (th - THRESHOLD) * BETA;                      \
            const float vd = v * DECAY + x;                                  \
            v  = (y != 0.0f) ? x : vd;                                       \
            y  = (v > th) ? 1.0f : 0.0f;                                     \
            __stcs(&ty[((c) * U + u) * BN + g], y);                          \
        }                                                                    \
    }

__global__ void __launch_bounds__(BLK) telif_kernel(
    const float* __restrict__ tx,
    const float* __restrict__ TE,
    float* __restrict__ ty)
{
    __shared__ float s_tx[DEPTH][U][BLK];     // 16 KB tx ring
    __shared__ float s_te[2][BLK][TEPAD];     // 36 KB TE double buffer

    const int g    = blockIdx.x * BLK + threadIdx.x;        // g = b*N + n
    const int n0   = (blockIdx.x & (N_DIM / BLK - 1)) * BLK;
    const int lane = threadIdx.x & 31;
    const int w    = threadIdx.x >> 5;

    // tx copy mapping (constant per thread)
    const int row_  = lane >> 3;                 // timestep within chunk
    const int seg_  = w * 32 + (lane & 7) * 4;   // float index within row
    const int gseg_ = blockIdx.x * BLK + seg_;
    const uint32_t smem_tx = (uint32_t)__cvta_generic_to_shared(s_tx);
    const uint32_t smem_te = (uint32_t)__cvta_generic_to_shared(s_te);

    float v  = REST;
    float y  = 0.0f;
    float th = THRESHOLD;

    // prologue: TE tile 0 rides with tx chunk 0's group; 7 tx chunks in flight
    TE_ASYNC(0)
    TX_ASYNC(0) TX_ASYNC(1) TX_ASYNC(2) TX_ASYNC(3)
    TX_ASYNC(4) TX_ASYNC(5) TX_ASYNC(6)

    // steady state: 8 chunks (one TE tile) per iteration, guard-free.
    // Computes chunks 0..119, issues tx 7..126 and TE tiles 1..15.
    #pragma unroll 1
    for (int c = 0; c < NCHUNK - 8; c += 8) {
        TE_ASYNC(c / 8 + 1)                      // joins group of tx chunk c+7
        TX_ASYNC(c + 7)  ARRIVE(7) COMPUTE_CHUNK(c + 0)
        TX_ASYNC(c + 8)  ARRIVE(7) COMPUTE_CHUNK(c + 1)
        TX_ASYNC(c + 9)  ARRIVE(7) COMPUTE_CHUNK(c + 2)
        TX_ASYNC(c + 10) ARRIVE(7) COMPUTE_CHUNK(c + 3)
        TX_ASYNC(c + 11) ARRIVE(7) COMPUTE_CHUNK(c + 4)
        TX_ASYNC(c + 12) ARRIVE(7) COMPUTE_CHUNK(c + 5)
        TX_ASYNC(c + 13) ARRIVE(7) COMPUTE_CHUNK(c + 6)
        TX_ASYNC(c + 14) ARRIVE(7) COMPUTE_CHUNK(c + 7)
    }

    // drain: chunks 120..127 (TE tile 15 already landed with group 119)
    TX_ASYNC(127) ARRIVE(7) COMPUTE_CHUNK(120)
    ARRIVE(6) COMPUTE_CHUNK(121)
    ARRIVE(5) COMPUTE_CHUNK(122)
    ARRIVE(4) COMPUTE_CHUNK(123)
    ARRIVE(3) COMPUTE_CHUNK(124)
    ARRIVE(2) COMPUTE_CHUNK(125)
    ARRIVE(1) COMPUTE_CHUNK(126)
    ARRIVE(0) COMPUTE_CHUNK(127)
}

// ---------------------------------------------------------------------------
extern "C" void kernel_launch(void* const* d_in, const int* in_sizes, int n_in,
                              void* d_out, int out_size) {
    const float* tx = (const float*)d_in[0];   // [T, B, N]
    const float* TE = (const float*)d_in[1];   // [N, T]
    float* ty = (float*)d_out;                 // [T, B, N]
    (void)in_sizes; (void)n_in; (void)out_size;

    telif_kernel<<<BN / BLK, BLK>>>(tx, TE, ty);
}

// round 15
// speedup vs baseline: 1.1657x; 1.0419x over previous
#include <cuda_runtime.h>
#include <cuda_bf16.h>
#include <cstdint>

// TELIF: temporal-encoded LIF neuron scan — single kernel, no block barriers.
//   tx : [T, B, N] float32   (T=512, B=64, N=1024)
//   TE : [N, T]    float32
//   out: [T, B, N] float32 spikes
//
// Per (b, n), sequential in t:
//   th = th + v*TE[n,t] - (th - THRESHOLD)*BETA
//   v  = v*DECAY*(1 - y) + x
//   y  = (v > th) ? 1 : 0
//
// Both input streams are pipelined gmem->smem with cp.async; both copies are
// WARP-LOCAL (each warp copies exactly the floats its own lanes consume), so
// completion needs only cp.async.wait_group + __syncwarp — no __syncthreads.
//  - tx: depth-8 ring of 4-timestep chunks (one 16B op/thread/chunk).
//  - TE: double-buffered 32-timestep x 64-row tiles from the native [N,T]
//    layout (tile row = 128B; 4 full lines per warp-op; L2-resident).
//    Tile T+1 rides in the commit group of tx chunk 8T+7 (7-chunk lead).
// BLK=64 -> grid 1024: per-SM CTA count 7 vs mean 6.92 (wave efficiency
// ~99% vs 86.5% at grid 512), smem 26KB -> 8 CTAs/SM capacity, one wave.

#define T_STEPS 512
#define B_DIM   64
#define N_DIM   1024
#define BN      (B_DIM * N_DIM)      // 65536
#define U       4                    // timesteps per chunk
#define NCHUNK  (T_STEPS / U)        // 128
#define BLK     64
#define DEPTH   8                    // tx ring depth (chunks)
#define TS_TILE 32                   // timesteps per TE tile (= 8 chunks)
#define TEPAD   36                   // floats per TE smem row (conflict-free)

#define REST      0.0f
#define DECAY     0.2f
#define THRESHOLD 0.3f
#define BETA      0.02f

// ---------------------------------------------------------------------------
__device__ __forceinline__ void cp_async16(uint32_t dst, const void* src) {
    asm volatile("cp.async.cg.shared.global [%0], [%1], 16;"
                 :: "r"(dst), "l"(src));
}
#define CP_COMMIT()  asm volatile("cp.async.commit_group;" ::: "memory")
#define CP_WAIT(nn)  asm volatile("cp.async.wait_group " #nn ";" ::: "memory")
#define ARRIVE(nn)   { CP_WAIT(nn); __syncwarp(); }

// ---- TE tile T -> smem buffer T&1 (8 warp-local ops; NO commit: rides in
//      the next TX_ASYNC's group). Warp w copies rows w*32..w*32+31. --------
#define TE_ASYNC(T)                                                          \
    {                                                                        \
        const int bb = (T) & 1;                                              \
        _Pragma("unroll")                                                    \
        for (int j = 0; j < 8; j++) {                                        \
            const int rt = w * 32 + j * 4 + (lane >> 3);                     \
            cp_async16(smem_te +                                             \
                           (uint32_t)(((bb * BLK + rt) * TEPAD               \
                                       + (lane & 7) * 4) * 4u),              \
                       TE + (size_t)(n0 + rt) * T_STEPS + (T) * TS_TILE      \
                          + (lane & 7) * 4);                                 \
        }                                                                    \
    }

// ---- tx chunk c -> ring slot c%DEPTH (one 16B op/thread) + commit ---------
// Warp w copies (and later consumes) floats w*32..w*32+31 of each row.
#define TX_ASYNC(c)                                                          \
    {                                                                        \
        const int slot = (c) & (DEPTH - 1);                                  \
        cp_async16(smem_tx +                                                 \
                       (uint32_t)(((slot * U + row_) * BLK + seg_) * 4u),    \
                   tx + (size_t)((c) * U + row_) * BN + gseg_);              \
        CP_COMMIT();                                                         \
    }

// ---- one chunk of the recurrence (math form measured rel_err == 0.0) ------
#define COMPUTE_CHUNK(c)                                                     \
    {                                                                        \
        const int slot = (c) & (DEPTH - 1);                                  \
        const float4 t4 = *reinterpret_cast<const float4*>(                  \
            &s_te[((c) >> 3) & 1][threadIdx.x][((c) & 7) * 4]);              \
        _Pragma("unroll")                                                    \
        for (int u = 0; u < U; u++) {                                        \
            const float x  = s_tx[slot][u][threadIdx.x];                     \
            const float te = (u == 0) ? t4.x : (u == 1) ? t4.y               \
                           : (u == 2) ? t4.z : t4.w;                         \
            th = th + v * te - (th - THRESHOLD) * BETA;                      \
            const float vd = v * DECAY + x;                                  \
            v  = (y != 0.0f) ? x : vd;                                       \
            y  = (v > th) ? 1.0f : 0.0f;                                     \
            __stcs(&ty[((c) * U + u) * BN + g], y);                          \
        }                                                                    \
    }

__global__ void __launch_bounds__(BLK) telif_kernel(
    const float* __restrict__ tx,
    const float* __restrict__ TE,
    float* __restrict__ ty)
{
    __shared__ float s_tx[DEPTH][U][BLK];     // 8 KB tx ring
    __shared__ float s_te[2][BLK][TEPAD];     // 18 KB TE double buffer

    const int g    = blockIdx.x * BLK + threadIdx.x;        // g = b*N + n
    const int n0   = (blockIdx.x & (N_DIM / BLK - 1)) * BLK;
    const int lane = threadIdx.x & 31;
    const int w    = threadIdx.x >> 5;

    // tx copy mapping (constant per thread)
    const int row_  = lane >> 3;                 // timestep within chunk
    const int seg_  = w * 32 + (lane & 7) * 4;   // float index within row
    const int gseg_ = blockIdx.x * BLK + seg_;
    const uint32_t smem_tx = (uint32_t)__cvta_generic_to_shared(s_tx);
    const uint32_t smem_te = (uint32_t)__cvta_generic_to_shared(s_te);

    float v  = REST;
    float y  = 0.0f;
    float th = THRESHOLD;

    // prologue: TE tile 0 rides with tx chunk 0's group; 7 tx chunks in flight
    TE_ASYNC(0)
    TX_ASYNC(0) TX_ASYNC(1) TX_ASYNC(2) TX_ASYNC(3)
    TX_ASYNC(4) TX_ASYNC(5) TX_ASYNC(6)

    // steady state: 8 chunks (one TE tile) per iteration, guard-free.
    // Computes chunks 0..119, issues tx 7..126 and TE tiles 1..15.
    #pragma unroll 1
    for (int c = 0; c < NCHUNK - 8; c += 8) {
        TE_ASYNC(c / 8 + 1)                      // joins group of tx chunk c+7
        TX_ASYNC(c + 7)  ARRIVE(7) COMPUTE_CHUNK(c + 0)
        TX_ASYNC(c + 8)  ARRIVE(7) COMPUTE_CHUNK(c + 1)
        TX_ASYNC(c + 9)  ARRIVE(7) COMPUTE_CHUNK(c + 2)
        TX_ASYNC(c + 10) ARRIVE(7) COMPUTE_CHUNK(c + 3)
        TX_ASYNC(c + 11) ARRIVE(7) COMPUTE_CHUNK(c + 4)
        TX_ASYNC(c + 12) ARRIVE(7) COMPUTE_CHUNK(c + 5)
        TX_ASYNC(c + 13) ARRIVE(7) COMPUTE_CHUNK(c + 6)
        TX_ASYNC(c + 14) ARRIVE(7) COMPUTE_CHUNK(c + 7)
    }

    // drain: chunks 120..127 (TE tile 15 already landed with group 119)
    TX_ASYNC(127) ARRIVE(7) COMPUTE_CHUNK(120)
    ARRIVE(6) COMPUTE_CHUNK(121)
    ARRIVE(5) COMPUTE_CHUNK(122)
    ARRIVE(4) COMPUTE_CHUNK(123)
    ARRIVE(3) COMPUTE_CHUNK(124)
    ARRIVE(2) COMPUTE_CHUNK(125)
    ARRIVE(1) COMPUTE_CHUNK(126)
    ARRIVE(0) COMPUTE_CHUNK(127)
}

// ---------------------------------------------------------------------------
extern "C" void kernel_launch(void* const* d_in, const int* in_sizes, int n_in,
                              void* d_out, int out_size) {
    const float* tx = (const float*)d_in[0];   // [T, B, N]
    const float* TE = (const float*)d_in[1];   // [N, T]
    float* ty = (float*)d_out;                 // [T, B, N]
    (void)in_sizes; (void)n_in; (void)out_size;

    telif_kernel<<<BN / BLK, BLK>>>(tx, TE, ty);
}